// round 15
// baseline (speedup 1.0000x reference)
#include <cuda_runtime.h>
#include <cuda_bf16.h>
#include <cstdint>

#define N_NODES 50000
#define N_EDGES 800000
#define NODE_IN 16
#define NODE_OUT 3
#define H 128
#define N_LAYERS 3

// ---- mma tile params
#define ET 128                       // rows per block tile
#define NTILES (N_EDGES / ET)        // 6250
// node kernel smem — A2 overlays A1
#define A2H_OFF 0                    // [128][136] bf16 = 34816 B
#define A2L_OFF 34816
#define A1H_OFF 0
#define A1L_OFF 34816
#define BH_OFF  69632                // [128][72] bf16
#define BL_OFF  88064
#define NODE_SMEM 106496             // 2 CTAs/SM
// prep_p kernel smem
#define PA_H 0
#define PA_L 18432
#define PB_H 36864
#define PB_L 55296
#define PREP_SMEM 73728
// persistent edge kernel smem: A2 x2 buffers + resident B
#define EBUF_BYTES 69632             // one A2 buffer (hi+lo)
#define EB_H 139264                  // resident W2 hi [128][136]
#define EB_L 174080
#define EDGE_SMEM_P 208896
#define SA1 72
#define SB  72
#define SA2 136
#define SB2 136

typedef unsigned long long u64;

// ---------------------------------------------------------------------------
// Scratch (__device__ globals; alloc-free rule)
// ---------------------------------------------------------------------------
__device__ float g_h[N_NODES * H];
__device__ float g_agg[N_NODES * H];
__device__ float g_p1[N_NODES * H];            // h@W1_top + b1 (per layer)
__device__ float g_p2[N_NODES * H];            // h@W1_bot
__device__ __nv_bfloat16 g_hhi[N_NODES * H];   // persistent hi/lo split of h
__device__ __nv_bfloat16 g_hlo[N_NODES * H];
__device__ int   g_src[N_EDGES];
__device__ int   g_dst[N_EDGES];
__device__ int   g_is64;
// transposed hi/lo-split bf16 weights: w^T indexed [c][k]
__device__ __nv_bfloat16 g_ew1t[N_LAYERS][2][H][2 * H];
__device__ __nv_bfloat16 g_ew2t[N_LAYERS][2][H][H];
__device__ __nv_bfloat16 g_nw1t[N_LAYERS][2][H][2 * H];
__device__ __nv_bfloat16 g_nw2t[N_LAYERS][2][H][H];

// ---------------------------------------------------------------------------
// helpers
// ---------------------------------------------------------------------------
__device__ __forceinline__ uint32_t smem_u32(const void* p) {
    uint32_t a;
    asm("{ .reg .u64 t; cvta.to.shared.u64 t, %1; cvt.u32.u64 %0, t; }"
        : "=r"(a) : "l"(p));
    return a;
}
__device__ __forceinline__ void cp16(uint32_t saddr, const void* gptr) {
    asm volatile("cp.async.cg.shared.global [%0], [%1], 16;"
                 :: "r"(saddr), "l"(gptr) : "memory");
}
__device__ __forceinline__ void cp_commit_wait() {
    asm volatile("cp.async.commit_group;" ::: "memory");
    asm volatile("cp.async.wait_group 0;" ::: "memory");
}
__device__ __forceinline__ void ldm_x4(uint32_t* r, uint32_t addr) {
    asm volatile("ldmatrix.sync.aligned.m8n8.x4.shared.b16 {%0,%1,%2,%3}, [%4];"
                 : "=r"(r[0]), "=r"(r[1]), "=r"(r[2]), "=r"(r[3]) : "r"(addr));
}
__device__ __forceinline__ void mma_bf16(float* c, const uint32_t* a, const uint32_t* b) {
    asm volatile(
        "mma.sync.aligned.m16n8k16.row.col.f32.bf16.bf16.f32 "
        "{%0,%1,%2,%3}, {%4,%5,%6,%7}, {%8,%9}, {%0,%1,%2,%3};"
        : "+f"(c[0]), "+f"(c[1]), "+f"(c[2]), "+f"(c[3])
        : "r"(a[0]), "r"(a[1]), "r"(a[2]), "r"(a[3]), "r"(b[0]), "r"(b[1]));
}
__device__ __forceinline__ void split2(float a, float b, uint32_t& hi, uint32_t& lo) {
    __nv_bfloat16 ha = __float2bfloat16(a), hb = __float2bfloat16(b);
    hi = (uint32_t)__bfloat16_as_ushort(ha) | ((uint32_t)__bfloat16_as_ushort(hb) << 16);
    __nv_bfloat16 la = __float2bfloat16(a - __bfloat162float(ha));
    __nv_bfloat16 lb = __float2bfloat16(b - __bfloat162float(hb));
    lo = (uint32_t)__bfloat16_as_ushort(la) | ((uint32_t)__bfloat16_as_ushort(lb) << 16);
}
__device__ __forceinline__ void red_add_v2(float* p, float a, float b) {
    asm volatile("red.global.add.v2.f32 [%0], {%1, %2};"
                 :: "l"(p), "f"(a), "f"(b) : "memory");
}

// ---------------------------------------------------------------------------
// dtype probe + convert
// ---------------------------------------------------------------------------
__global__ void detect_kernel(const void* __restrict__ ei) {
    if (threadIdx.x == 0 && blockIdx.x == 0) {
        const long long* p = (const long long*)ei;
        int is64 = 1;
        for (int i = 0; i < 256; i++) {
            long long v = p[i];
            if (v < 0 || v >= N_NODES) { is64 = 0; break; }
        }
        g_is64 = is64;
    }
}

__global__ void convert_kernel(const void* __restrict__ ei) {
    int i = blockIdx.x * blockDim.x + threadIdx.x;
    if (i >= 2 * N_EDGES) return;
    int v;
    if (g_is64) v = (int)((const long long*)ei)[i];
    else        v = ((const int*)ei)[i];
    if (i < N_EDGES) g_src[i] = v;
    else             g_dst[i - N_EDGES] = v;
}

// ---------------------------------------------------------------------------
// Weight prep: transposed hi/lo-split bf16 (w^T [c][k]) for edge + node MLPs
// ---------------------------------------------------------------------------
__global__ void prep_w_kernel(const float* __restrict__ e_w1,
                              const float* __restrict__ e_w2,
                              const float* __restrict__ n_w1,
                              const float* __restrict__ n_w2) {
    int idx = blockIdx.x * blockDim.x + threadIdx.x;
    const int W1E = N_LAYERS * 2 * H * H;
    const int W2E = N_LAYERS * H * H;
    if (idx < 2 * (W1E + W2E)) {
        int which = idx >= (W1E + W2E);               // 0 = edge, 1 = node
        int j = idx - which * (W1E + W2E);
        if (j < W1E) {
            int l = j / (2 * H * H);
            int rem = j % (2 * H * H);
            int k = rem / H, c = rem % H;
            float w = which ? n_w1[j] : e_w1[j];
            __nv_bfloat16 hi = __float2bfloat16(w);
            __nv_bfloat16 lo = __float2bfloat16(w - __bfloat162float(hi));
            if (which) { g_nw1t[l][0][c][k] = hi; g_nw1t[l][1][c][k] = lo; }
            else       { g_ew1t[l][0][c][k] = hi; g_ew1t[l][1][c][k] = lo; }
        } else {
            int q = j - W1E;
            int l = q / (H * H);
            int rem = q % (H * H);
            int k = rem / H, c = rem % H;
            float w = which ? n_w2[q] : e_w2[q];
            __nv_bfloat16 hi = __float2bfloat16(w);
            __nv_bfloat16 lo = __float2bfloat16(w - __bfloat162float(hi));
            if (which) { g_nw2t[l][0][c][k] = hi; g_nw2t[l][1][c][k] = lo; }
            else       { g_ew2t[l][0][c][k] = hi; g_ew2t[l][1][c][k] = lo; }
        }
    }
}

// ---------------------------------------------------------------------------
// Encoder (+ zero g_agg + write hi/lo split)
// ---------------------------------------------------------------------------
__global__ void enc_kernel(const float* __restrict__ x,
                           const float* __restrict__ w,
                           const float* __restrict__ b) {
    int idx = blockIdx.x * blockDim.x + threadIdx.x;
    if (idx >= N_NODES * H) return;
    int node = idx >> 7;
    int c = idx & (H - 1);
    float acc = b[c];
#pragma unroll
    for (int k = 0; k < NODE_IN; k++)
        acc = fmaf(x[node * NODE_IN + k], w[k * H + c], acc);
    g_h[idx] = acc;
    g_agg[idx] = 0.0f;
    __nv_bfloat16 hi = __float2bfloat16(acc);
    g_hhi[idx] = hi;
    g_hlo[idx] = __float2bfloat16(acc - __bfloat162float(hi));
}

// ---------------------------------------------------------------------------
// mma chunk: C += A(hi/lo)[rows r0..+31][k 0..63] x B^T cols c0w..+63 (3-pass)
// bstride parametrized; b base pre-offset for k-chunk.
// ---------------------------------------------------------------------------
__device__ __forceinline__ void mma_chunk(
    uint32_t a_hi, uint32_t a_lo, int astride,
    uint32_t b_hi, uint32_t b_lo, int bstride,
    float C[2][8][4], int r0, int c0w, int lane)
{
    const int arow = lane & 15;
    const int acol = (lane >> 4) * 8;
    const int brow = (lane & 7) + ((lane >> 4) << 3);
    const int bcol = ((lane >> 3) & 1) * 8;
#pragma unroll
    for (int ks = 0; ks < 4; ks++) {
        uint32_t ah[2][4], al[2][4], bh[4][4], bl[4][4];
#pragma unroll
        for (int i = 0; i < 2; i++) {
            uint32_t off = (uint32_t)(((r0 + i * 16 + arow) * astride + ks * 16 + acol) * 2);
            ldm_x4(ah[i], a_hi + off);
            ldm_x4(al[i], a_lo + off);
        }
#pragma unroll
        for (int p = 0; p < 4; p++) {
            uint32_t off = (uint32_t)(((c0w + p * 16 + brow) * bstride + ks * 16 + bcol) * 2);
            ldm_x4(bh[p], b_hi + off);
            ldm_x4(bl[p], b_lo + off);
        }
#pragma unroll
        for (int i = 0; i < 2; i++)
#pragma unroll
            for (int p = 0; p < 4; p++) {
                mma_bf16(C[i][2 * p],     ah[i], &bh[p][0]);
                mma_bf16(C[i][2 * p],     ah[i], &bl[p][0]);
                mma_bf16(C[i][2 * p],     al[i], &bh[p][0]);
                mma_bf16(C[i][2 * p + 1], ah[i], &bh[p][2]);
                mma_bf16(C[i][2 * p + 1], ah[i], &bl[p][2]);
                mma_bf16(C[i][2 * p + 1], al[i], &bh[p][2]);
            }
    }
}

// ---------------------------------------------------------------------------
// prep_p kernel: P1 = h@W1_top + b1, P2 = h@W1_bot   (per 128-node tile)
// ---------------------------------------------------------------------------
__global__ __launch_bounds__(256, 2)
void prep_p_kernel(const float* __restrict__ b1, int layer) {
    extern __shared__ char smem[];
    const uint32_t sbase = smem_u32(smem);
    const int tid = threadIdx.x;
    const int lane = tid & 31;
    const int wid = tid >> 5;
    const int n0 = blockIdx.x * ET;

    const int srow = tid >> 1;
    const int shalf = tid & 1;
    const int snode = n0 + srow;
    const int scn = snode < N_NODES ? snode : (N_NODES - 1);

    const int r0 = (wid >> 1) * 32;
    const int c0w = (wid & 1) * 64;

    const uint32_t pah = sbase + PA_H + srow * (SA1 * 2) + shalf * 64;
    const uint32_t pal = sbase + PA_L + srow * (SA1 * 2) + shalf * 64;
    const uint32_t pbh = sbase + PB_H + srow * (SB * 2) + shalf * 64;
    const uint32_t pbl = sbase + PB_L + srow * (SB * 2) + shalf * 64;

    for (int out = 0; out < 2; out++) {
        float C[2][8][4];
#pragma unroll
        for (int i = 0; i < 2; i++)
#pragma unroll
            for (int j = 0; j < 8; j++)
#pragma unroll
                for (int q = 0; q < 4; q++) C[i][j][q] = 0.0f;

        for (int kc = 0; kc < 2; kc++) {
            {
                size_t goff = (size_t)scn * H + kc * 64 + shalf * 32;
                const __nv_bfloat16* sh = &g_hhi[goff];
                const __nv_bfloat16* sl = &g_hlo[goff];
#pragma unroll
                for (int i = 0; i < 4; i++) {
                    cp16(pah + i * 16, sh + i * 8);
                    cp16(pal + i * 16, sl + i * 8);
                }
            }
            {
                int koff = out * 128 + kc * 64 + shalf * 32;
                const __nv_bfloat16* sh = &g_ew1t[layer][0][srow][koff];
                const __nv_bfloat16* sl = &g_ew1t[layer][1][srow][koff];
#pragma unroll
                for (int i = 0; i < 4; i++) {
                    cp16(pbh + i * 16, sh + i * 8);
                    cp16(pbl + i * 16, sl + i * 8);
                }
            }
            cp_commit_wait();
            __syncthreads();
            mma_chunk(sbase + PA_H, sbase + PA_L, SA1,
                      sbase + PB_H, sbase + PB_L, SB, C, r0, c0w, lane);
            __syncthreads();
        }

        float* dst = out ? g_p2 : g_p1;
#pragma unroll
        for (int i = 0; i < 2; i++) {
            int row = r0 + i * 16 + (lane >> 2);
            int nd0 = n0 + row;
            int nd1 = n0 + row + 8;
#pragma unroll
            for (int j = 0; j < 8; j++) {
                int col = c0w + j * 8 + (lane & 3) * 2;
                float bb0 = out ? 0.0f : b1[col];
                float bb1 = out ? 0.0f : b1[col + 1];
                if (nd0 < N_NODES)
                    *(float2*)&dst[(size_t)nd0 * H + col] =
                        make_float2(C[i][j][0] + bb0, C[i][j][1] + bb1);
                if (nd1 < N_NODES)
                    *(float2*)&dst[(size_t)nd1 * H + col] =
                        make_float2(C[i][j][2] + bb0, C[i][j][3] + bb1);
            }
        }
    }
}

// ---------------------------------------------------------------------------
// Persistent edge kernel: W2 resident in smem, A2 double-buffered.
// e = relu(P1[src] + P2[dst]) @ W2 + b2 ; scatter into g_agg.
// ---------------------------------------------------------------------------
__device__ __forceinline__ void edge_build_tile(char* smem, int t, int buf,
                                                int srow, int shalf) {
    int e = t * ET + srow;
    int src = g_src[e];
    int dst = g_dst[e];
    const float4* p1 = (const float4*)&g_p1[(size_t)src * H + shalf * 64];
    const float4* p2 = (const float4*)&g_p2[(size_t)dst * H + shalf * 64];
    char* ah = smem + buf * EBUF_BYTES + srow * (SA2 * 2) + shalf * 128;
    char* al = smem + buf * EBUF_BYTES + 34816 + srow * (SA2 * 2) + shalf * 128;
#pragma unroll
    for (int i = 0; i < 16; i++) {
        float4 a = p1[i];
        float4 b = p2[i];
        float v0 = fmaxf(a.x + b.x, 0.0f);
        float v1 = fmaxf(a.y + b.y, 0.0f);
        float v2 = fmaxf(a.z + b.z, 0.0f);
        float v3 = fmaxf(a.w + b.w, 0.0f);
        uint32_t h01, l01, h23, l23;
        split2(v0, v1, h01, l01);
        split2(v2, v3, h23, l23);
        *(uint2*)(ah + i * 8) = make_uint2(h01, h23);
        *(uint2*)(al + i * 8) = make_uint2(l01, l23);
    }
}

__global__ __launch_bounds__(256, 1)
void edge_kernel_pers(const float* __restrict__ b2, int layer) {
    extern __shared__ char smem[];
    const uint32_t sbase = smem_u32(smem);
    const int tid = threadIdx.x;
    const int lane = tid & 31;
    const int wid = tid >> 5;
    const int srow = tid >> 1;
    const int shalf = tid & 1;
    const int r0 = (wid >> 1) * 32;
    const int c0w = (wid & 1) * 64;
    const int G = gridDim.x;

    // ---- stage resident B = W2^T hi/lo into [128][SB2]
    {
        const __nv_bfloat16* sh = &g_ew2t[layer][0][srow][shalf * 64];
        const __nv_bfloat16* sl = &g_ew2t[layer][1][srow][shalf * 64];
        uint32_t dh = sbase + EB_H + (uint32_t)(srow * SB2 + shalf * 64) * 2;
        uint32_t dl = sbase + EB_L + (uint32_t)(srow * SB2 + shalf * 64) * 2;
#pragma unroll
        for (int i = 0; i < 8; i++) {
            cp16(dh + i * 16, sh + i * 8);
            cp16(dl + i * 16, sl + i * 8);
        }
    }

    // preload bias pairs
    float2 bb[8];
#pragma unroll
    for (int j = 0; j < 8; j++)
        bb[j] = *(const float2*)&b2[c0w + j * 8 + (lane & 3) * 2];

    int t = blockIdx.x;
    if (t < NTILES) edge_build_tile(smem, t, 0, srow, shalf);
    cp_commit_wait();

    int it = 0;
    for (; t < NTILES; t += G, it++) {
        int cur = it & 1;
        __syncthreads();
        float C[2][8][4];
#pragma unroll
        for (int i = 0; i < 2; i++)
#pragma unroll
            for (int j = 0; j < 8; j++)
#pragma unroll
                for (int q = 0; q < 4; q++) C[i][j][q] = 0.0f;

#pragma unroll
        for (int kc = 0; kc < 2; kc++)
            mma_chunk(sbase + cur * EBUF_BYTES + kc * 128,
                      sbase + cur * EBUF_BYTES + 34816 + kc * 128, SA2,
                      sbase + EB_H + kc * 128, sbase + EB_L + kc * 128, SB2,
                      C, r0, c0w, lane);

        int nt = t + G;
        if (nt < NTILES) edge_build_tile(smem, nt, cur ^ 1, srow, shalf);

        // scatter
#pragma unroll
        for (int i = 0; i < 2; i++) {
            int row = r0 + i * 16 + (lane >> 2);
            int d0 = g_dst[t * ET + row];
            int d1 = g_dst[t * ET + row + 8];
#pragma unroll
            for (int j = 0; j < 8; j++) {
                int col = c0w + j * 8 + (lane & 3) * 2;
                red_add_v2(&g_agg[(size_t)d0 * H + col],
                           C[i][j][0] + bb[j].x, C[i][j][1] + bb[j].y);
                red_add_v2(&g_agg[(size_t)d1 * H + col],
                           C[i][j][2] + bb[j].x, C[i][j][3] + bb[j].y);
            }
        }
    }
}

// ---------------------------------------------------------------------------
// Node kernel (tensor-core mma.sync): 128 nodes/block; h += MLP([h,agg]);
// zeroes agg in place; writes fp32 h + bf16 hi/lo split for next layer.
// ---------------------------------------------------------------------------
__global__ __launch_bounds__(256, 2)
void node_kernel_mma(const float* __restrict__ b1,
                     const float* __restrict__ b2, int layer) {
    extern __shared__ char smem[];
    const uint32_t sbase = smem_u32(smem);
    const int tid = threadIdx.x;
    const int lane = tid & 31;
    const int wid = tid >> 5;
    const int n0 = blockIdx.x * ET;

    const int srow = tid >> 1;
    const int shalf = tid & 1;
    const int snode = n0 + srow;
    const int scn = snode < N_NODES ? snode : (N_NODES - 1);

    const int r0 = (wid >> 1) * 32;
    const int c0w = (wid & 1) * 64;

    const uint32_t a1h = sbase + A1H_OFF + srow * (SA1 * 2) + shalf * 64;
    const uint32_t a1l = sbase + A1L_OFF + srow * (SA1 * 2) + shalf * 64;
    const uint32_t bsh = sbase + BH_OFF + srow * (SB * 2) + shalf * 64;
    const uint32_t bsl = sbase + BL_OFF + srow * (SB * 2) + shalf * 64;

    float C[2][8][4];
#pragma unroll
    for (int i = 0; i < 2; i++)
#pragma unroll
        for (int j = 0; j < 8; j++)
#pragma unroll
            for (int q = 0; q < 4; q++) C[i][j][q] = 0.0f;

    // ================= GEMM1: K=256 ([h | agg]) in 4 chunks =================
    for (int kc = 0; kc < 4; kc++) {
        if (kc < 2) {
            size_t goff = (size_t)scn * H + kc * 64 + shalf * 32;
            const __nv_bfloat16* sh = &g_hhi[goff];
            const __nv_bfloat16* sl = &g_hlo[goff];
#pragma unroll
            for (int i = 0; i < 4; i++) {
                cp16(a1h + i * 16, sh + i * 8);
                cp16(a1l + i * 16, sl + i * 8);
            }
        } else {
            // agg chunks: split on the fly + zero in place
            float4* hp = (float4*)&g_agg[(size_t)scn * H + (kc & 1) * 64 + shalf * 32];
            uint32_t ph[16], pl[16];
#pragma unroll
            for (int i = 0; i < 8; i++) {
                float4 v = hp[i];
                split2(v.x, v.y, ph[2 * i],     pl[2 * i]);
                split2(v.z, v.w, ph[2 * i + 1], pl[2 * i + 1]);
            }
            if (snode < N_NODES) {
                float4 z = make_float4(0.f, 0.f, 0.f, 0.f);
#pragma unroll
                for (int i = 0; i < 8; i++) hp[i] = z;
            }
            uint4* dh = (uint4*)(smem + A1H_OFF + srow * (SA1 * 2) + shalf * 64);
            uint4* dl = (uint4*)(smem + A1L_OFF + srow * (SA1 * 2) + shalf * 64);
#pragma unroll
            for (int i = 0; i < 4; i++) {
                dh[i] = make_uint4(ph[4 * i], ph[4 * i + 1], ph[4 * i + 2], ph[4 * i + 3]);
                dl[i] = make_uint4(pl[4 * i], pl[4 * i + 1], pl[4 * i + 2], pl[4 * i + 3]);
            }
        }
        {
            const __nv_bfloat16* sh = &g_nw1t[layer][0][srow][kc * 64 + shalf * 32];
            const __nv_bfloat16* sl = &g_nw1t[layer][1][srow][kc * 64 + shalf * 32];
#pragma unroll
            for (int i = 0; i < 4; i++) {
                cp16(bsh + i * 16, sh + i * 8);
                cp16(bsl + i * 16, sl + i * 8);
            }
        }
        cp_commit_wait();
        __syncthreads();
        mma_chunk(sbase + A1H_OFF, sbase + A1L_OFF, SA1,
                  sbase + BH_OFF, sbase + BL_OFF, SB, C, r0, c0w, lane);
        __syncthreads();
    }

    // ===== Epilogue1 + stage GEMM2 B(kc=0) =====
    {
        const __nv_bfloat16* sh = &g_nw2t[layer][0][srow][shalf * 32];
        const __nv_bfloat16* sl = &g_nw2t[layer][1][srow][shalf * 32];
#pragma unroll
        for (int i = 0; i < 4; i++) {
            cp16(bsh + i * 16, sh + i * 8);
            cp16(bsl + i * 16, sl + i * 8);
        }
    }
#pragma unroll
    for (int i = 0; i < 2; i++)
#pragma unroll
        for (int j = 0; j < 8; j++) {
            int col = c0w + j * 8 + (lane & 3) * 2;
            int row = r0 + i * 16 + (lane >> 2);
            float bb0 = b1[col], bb1 = b1[col + 1];
            uint32_t hi, lo;
            split2(fmaxf(C[i][j][0] + bb0, 0.0f), fmaxf(C[i][j][1] + bb1, 0.0f), hi, lo);
            *(uint32_t*)(smem + A2H_OFF + row * (SA2 * 2) + col * 2) = hi;
            *(uint32_t*)(smem + A2L_OFF + row * (SA2 * 2) + col * 2) = lo;
            split2(fmaxf(C[i][j][2] + bb0, 0.0f), fmaxf(C[i][j][3] + bb1, 0.0f), hi, lo);
            *(uint32_t*)(smem + A2H_OFF + (row + 8) * (SA2 * 2) + col * 2) = hi;
            *(uint32_t*)(smem + A2L_OFF + (row + 8) * (SA2 * 2) + col * 2) = lo;
        }
    cp_commit_wait();
    __syncthreads();

    // ================= GEMM2: K=128 in 2 chunks =================
#pragma unroll
    for (int i = 0; i < 2; i++)
#pragma unroll
        for (int j = 0; j < 8; j++)
#pragma unroll
            for (int q = 0; q < 4; q++) C[i][j][q] = 0.0f;

    for (int kc = 0; kc < 2; kc++) {
        if (kc > 0) {
            const __nv_bfloat16* sh = &g_nw2t[layer][0][srow][kc * 64 + shalf * 32];
            const __nv_bfloat16* sl = &g_nw2t[layer][1][srow][kc * 64 + shalf * 32];
#pragma unroll
            for (int i = 0; i < 4; i++) {
                cp16(bsh + i * 16, sh + i * 8);
                cp16(bsl + i * 16, sl + i * 8);
            }
            cp_commit_wait();
            __syncthreads();
        }
        mma_chunk(sbase + A2H_OFF + kc * 128, sbase + A2L_OFF + kc * 128, SA2,
                  sbase + BH_OFF, sbase + BL_OFF, SB, C, r0, c0w, lane);
        __syncthreads();
    }

    // ======== Epilogue2: residual h += C + b2; write fp32 + bf16 split ========
#pragma unroll
    for (int i = 0; i < 2; i++) {
        int row = r0 + i * 16 + (lane >> 2);
        int nd0 = n0 + row;
        int nd1 = n0 + row + 8;
#pragma unroll
        for (int j = 0; j < 8; j++) {
            int col = c0w + j * 8 + (lane & 3) * 2;
            float bb0 = b2[col], bb1 = b2[col + 1];
            if (nd0 < N_NODES) {
                size_t off = (size_t)nd0 * H + col;
                float2* p = (float2*)&g_h[off];
                float2 v = *p;
                v.x += C[i][j][0] + bb0;
                v.y += C[i][j][1] + bb1;
                *p = v;
                uint32_t hi, lo;
                split2(v.x, v.y, hi, lo);
                *(uint32_t*)&g_hhi[off] = hi;
                *(uint32_t*)&g_hlo[off] = lo;
            }
            if (nd1 < N_NODES) {
                size_t off = (size_t)nd1 * H + col;
                float2* p = (float2*)&g_h[off];
                float2 v = *p;
                v.x += C[i][j][2] + bb0;
                v.y += C[i][j][3] + bb1;
                *p = v;
                uint32_t hi, lo;
                split2(v.x, v.y, hi, lo);
                *(uint32_t*)&g_hhi[off] = hi;
                *(uint32_t*)&g_hlo[off] = lo;
            }
        }
    }
}

// ---------------------------------------------------------------------------
// Decoder
// ---------------------------------------------------------------------------
__global__ void dec_kernel(const float* __restrict__ w,
                           const float* __restrict__ b,
                           float* __restrict__ out) {
    int idx = blockIdx.x * blockDim.x + threadIdx.x;
    if (idx >= N_NODES * NODE_OUT) return;
    int node = idx / NODE_OUT;
    int j = idx - node * NODE_OUT;
    float acc = b[j];
    const float* hp = &g_h[(size_t)node * H];
#pragma unroll 8
    for (int k = 0; k < H; k++)
        acc = fmaf(hp[k], w[k * NODE_OUT + j], acc);
    out[idx] = acc;
}

// ---------------------------------------------------------------------------
extern "C" void kernel_launch(void* const* d_in, const int* in_sizes, int n_in,
                              void* d_out, int out_size) {
    const float* x      = (const float*)d_in[0];
    const void*  ei     = d_in[1];
    const float* enc_w  = (const float*)d_in[2];
    const float* enc_b  = (const float*)d_in[3];
    const float* dec_w  = (const float*)d_in[4];
    const float* dec_b  = (const float*)d_in[5];
    const float* e_w1   = (const float*)d_in[6];
    const float* e_b1   = (const float*)d_in[7];
    const float* e_w2   = (const float*)d_in[8];
    const float* e_b2   = (const float*)d_in[9];
    const float* n_w1   = (const float*)d_in[10];
    const float* n_b1   = (const float*)d_in[11];
    const float* n_w2   = (const float*)d_in[12];
    const float* n_b2   = (const float*)d_in[13];
    float*       out    = (float*)d_out;

    static int nsm = 0;
    if (!nsm) {
        cudaFuncSetAttribute(edge_kernel_pers, cudaFuncAttributeMaxDynamicSharedMemorySize,
                             EDGE_SMEM_P);
        cudaFuncSetAttribute(node_kernel_mma, cudaFuncAttributeMaxDynamicSharedMemorySize,
                             NODE_SMEM);
        cudaFuncSetAttribute(prep_p_kernel, cudaFuncAttributeMaxDynamicSharedMemorySize,
                             PREP_SMEM);
        cudaDeviceGetAttribute(&nsm, cudaDevAttrMultiProcessorCount, 0);
        if (nsm <= 0) nsm = 148;
    }

    detect_kernel<<<1, 32>>>(ei);
    convert_kernel<<<(2 * N_EDGES + 255) / 256, 256>>>(ei);
    prep_w_kernel<<<(2 * N_LAYERS * (2 * H * H + H * H) + 255) / 256, 256>>>(
        e_w1, e_w2, n_w1, n_w2);
    enc_kernel<<<(N_NODES * H + 255) / 256, 256>>>(x, enc_w, enc_b);

    const int node_blocks = (N_NODES + ET - 1) / ET;
    for (int l = 0; l < N_LAYERS; l++) {
        prep_p_kernel<<<node_blocks, 256, PREP_SMEM>>>(e_b1 + (size_t)l * H, l);
        edge_kernel_pers<<<nsm, 256, EDGE_SMEM_P>>>(e_b2 + (size_t)l * H, l);
        node_kernel_mma<<<node_blocks, 256, NODE_SMEM>>>(
            n_b1 + (size_t)l * H, n_b2 + (size_t)l * H, l);
    }

    dec_kernel<<<(N_NODES * NODE_OUT + 255) / 256, 256>>>(dec_w, dec_b, out);
}

// round 17
// speedup vs baseline: 1.0918x; 1.0918x over previous
#include <cuda_runtime.h>
#include <cuda_bf16.h>
#include <cstdint>

#define N_NODES 50000
#define N_EDGES 800000
#define NODE_IN 16
#define NODE_OUT 3
#define H 128
#define N_LAYERS 3

// ---- mma tile params
#define ET 128                       // rows per block tile (prep/node kernels)
// node kernel smem — A2 overlays A1
#define A2H_OFF 0                    // [128][136] bf16 = 34816 B
#define A2L_OFF 34816
#define A1H_OFF 0
#define A1L_OFF 34816
#define BH_OFF  69632                // [128][72] bf16
#define BL_OFF  88064
#define NODE_SMEM 106496             // 2 CTAs/SM
// prep_p kernel smem
#define PA_H 0
#define PA_L 18432
#define PB_H 36864
#define PB_L 55296
#define PREP_SMEM 73728
// edge kernel (resident-B, occ-2): A2 [64][136] hi/lo + B [128][136] hi/lo
#define ET2 64
#define NT2 (N_EDGES / ET2)          // 12500
#define E_A2H 0
#define E_A2L 17408
#define E_BH  34816
#define E_BL  69632
#define E_SMEM 104448                // 2 CTAs/SM
#define SA1 72
#define SB  72
#define SA2 136
#define SE2 136

typedef unsigned long long u64;

// ---------------------------------------------------------------------------
// Scratch (__device__ globals; alloc-free rule)
// ---------------------------------------------------------------------------
__device__ float g_h[N_NODES * H];
__device__ float g_agg[N_NODES * H];
__device__ float g_p1[N_NODES * H];            // h@W1_top + b1 (per layer)
__device__ float g_p2[N_NODES * H];            // h@W1_bot
__device__ __nv_bfloat16 g_hhi[N_NODES * H];   // persistent hi/lo split of h
__device__ __nv_bfloat16 g_hlo[N_NODES * H];
__device__ int   g_src[N_EDGES];
__device__ int   g_dst[N_EDGES];
__device__ int   g_is64;
// transposed hi/lo-split bf16 weights: w^T indexed [c][k]
__device__ __nv_bfloat16 g_ew1t[N_LAYERS][2][H][2 * H];
__device__ __nv_bfloat16 g_ew2t[N_LAYERS][2][H][H];
__device__ __nv_bfloat16 g_nw1t[N_LAYERS][2][H][2 * H];
__device__ __nv_bfloat16 g_nw2t[N_LAYERS][2][H][H];

// ---------------------------------------------------------------------------
// helpers
// ---------------------------------------------------------------------------
__device__ __forceinline__ uint32_t smem_u32(const void* p) {
    uint32_t a;
    asm("{ .reg .u64 t; cvta.to.shared.u64 t, %1; cvt.u32.u64 %0, t; }"
        : "=r"(a) : "l"(p));
    return a;
}
__device__ __forceinline__ void cp16(uint32_t saddr, const void* gptr) {
    asm volatile("cp.async.cg.shared.global [%0], [%1], 16;"
                 :: "r"(saddr), "l"(gptr) : "memory");
}
__device__ __forceinline__ void cp_commit_wait() {
    asm volatile("cp.async.commit_group;" ::: "memory");
    asm volatile("cp.async.wait_group 0;" ::: "memory");
}
__device__ __forceinline__ void ldm_x4(uint32_t* r, uint32_t addr) {
    asm volatile("ldmatrix.sync.aligned.m8n8.x4.shared.b16 {%0,%1,%2,%3}, [%4];"
                 : "=r"(r[0]), "=r"(r[1]), "=r"(r[2]), "=r"(r[3]) : "r"(addr));
}
__device__ __forceinline__ void mma_bf16(float* c, const uint32_t* a, const uint32_t* b) {
    asm volatile(
        "mma.sync.aligned.m16n8k16.row.col.f32.bf16.bf16.f32 "
        "{%0,%1,%2,%3}, {%4,%5,%6,%7}, {%8,%9}, {%0,%1,%2,%3};"
        : "+f"(c[0]), "+f"(c[1]), "+f"(c[2]), "+f"(c[3])
        : "r"(a[0]), "r"(a[1]), "r"(a[2]), "r"(a[3]), "r"(b[0]), "r"(b[1]));
}
__device__ __forceinline__ void split2(float a, float b, uint32_t& hi, uint32_t& lo) {
    __nv_bfloat16 ha = __float2bfloat16(a), hb = __float2bfloat16(b);
    hi = (uint32_t)__bfloat16_as_ushort(ha) | ((uint32_t)__bfloat16_as_ushort(hb) << 16);
    __nv_bfloat16 la = __float2bfloat16(a - __bfloat162float(ha));
    __nv_bfloat16 lb = __float2bfloat16(b - __bfloat162float(hb));
    lo = (uint32_t)__bfloat16_as_ushort(la) | ((uint32_t)__bfloat16_as_ushort(lb) << 16);
}
__device__ __forceinline__ void red_add_v2(float* p, float a, float b) {
    asm volatile("red.global.add.v2.f32 [%0], {%1, %2};"
                 :: "l"(p), "f"(a), "f"(b) : "memory");
}

// ---------------------------------------------------------------------------
// dtype probe + convert
// ---------------------------------------------------------------------------
__global__ void detect_kernel(const void* __restrict__ ei) {
    if (threadIdx.x == 0 && blockIdx.x == 0) {
        const long long* p = (const long long*)ei;
        int is64 = 1;
        for (int i = 0; i < 256; i++) {
            long long v = p[i];
            if (v < 0 || v >= N_NODES) { is64 = 0; break; }
        }
        g_is64 = is64;
    }
}

__global__ void convert_kernel(const void* __restrict__ ei) {
    int i = blockIdx.x * blockDim.x + threadIdx.x;
    if (i >= 2 * N_EDGES) return;
    int v;
    if (g_is64) v = (int)((const long long*)ei)[i];
    else        v = ((const int*)ei)[i];
    if (i < N_EDGES) g_src[i] = v;
    else             g_dst[i - N_EDGES] = v;
}

// ---------------------------------------------------------------------------
// Weight prep: transposed hi/lo-split bf16 (w^T [c][k]) for edge + node MLPs
// ---------------------------------------------------------------------------
__global__ void prep_w_kernel(const float* __restrict__ e_w1,
                              const float* __restrict__ e_w2,
                              const float* __restrict__ n_w1,
                              const float* __restrict__ n_w2) {
    int idx = blockIdx.x * blockDim.x + threadIdx.x;
    const int W1E = N_LAYERS * 2 * H * H;
    const int W2E = N_LAYERS * H * H;
    if (idx < 2 * (W1E + W2E)) {
        int which = idx >= (W1E + W2E);               // 0 = edge, 1 = node
        int j = idx - which * (W1E + W2E);
        if (j < W1E) {
            int l = j / (2 * H * H);
            int rem = j % (2 * H * H);
            int k = rem / H, c = rem % H;
            float w = which ? n_w1[j] : e_w1[j];
            __nv_bfloat16 hi = __float2bfloat16(w);
            __nv_bfloat16 lo = __float2bfloat16(w - __bfloat162float(hi));
            if (which) { g_nw1t[l][0][c][k] = hi; g_nw1t[l][1][c][k] = lo; }
            else       { g_ew1t[l][0][c][k] = hi; g_ew1t[l][1][c][k] = lo; }
        } else {
            int q = j - W1E;
            int l = q / (H * H);
            int rem = q % (H * H);
            int k = rem / H, c = rem % H;
            float w = which ? n_w2[q] : e_w2[q];
            __nv_bfloat16 hi = __float2bfloat16(w);
            __nv_bfloat16 lo = __float2bfloat16(w - __bfloat162float(hi));
            if (which) { g_nw2t[l][0][c][k] = hi; g_nw2t[l][1][c][k] = lo; }
            else       { g_ew2t[l][0][c][k] = hi; g_ew2t[l][1][c][k] = lo; }
        }
    }
}

// ---------------------------------------------------------------------------
// Encoder (+ zero g_agg + write hi/lo split)
// ---------------------------------------------------------------------------
__global__ void enc_kernel(const float* __restrict__ x,
                           const float* __restrict__ w,
                           const float* __restrict__ b) {
    int idx = blockIdx.x * blockDim.x + threadIdx.x;
    if (idx >= N_NODES * H) return;
    int node = idx >> 7;
    int c = idx & (H - 1);
    float acc = b[c];
#pragma unroll
    for (int k = 0; k < NODE_IN; k++)
        acc = fmaf(x[node * NODE_IN + k], w[k * H + c], acc);
    g_h[idx] = acc;
    g_agg[idx] = 0.0f;
    __nv_bfloat16 hi = __float2bfloat16(acc);
    g_hhi[idx] = hi;
    g_hlo[idx] = __float2bfloat16(acc - __bfloat162float(hi));
}

// ---------------------------------------------------------------------------
// mma chunk (M=32/warp variant, used by prep_p + node kernels)
// ---------------------------------------------------------------------------
__device__ __forceinline__ void mma_chunk(
    uint32_t a_hi, uint32_t a_lo, int astride,
    uint32_t b_hi, uint32_t b_lo, int bstride,
    float C[2][8][4], int r0, int c0w, int lane)
{
    const int arow = lane & 15;
    const int acol = (lane >> 4) * 8;
    const int brow = (lane & 7) + ((lane >> 4) << 3);
    const int bcol = ((lane >> 3) & 1) * 8;
#pragma unroll
    for (int ks = 0; ks < 4; ks++) {
        uint32_t ah[2][4], al[2][4], bh[4][4], bl[4][4];
#pragma unroll
        for (int i = 0; i < 2; i++) {
            uint32_t off = (uint32_t)(((r0 + i * 16 + arow) * astride + ks * 16 + acol) * 2);
            ldm_x4(ah[i], a_hi + off);
            ldm_x4(al[i], a_lo + off);
        }
#pragma unroll
        for (int p = 0; p < 4; p++) {
            uint32_t off = (uint32_t)(((c0w + p * 16 + brow) * bstride + ks * 16 + bcol) * 2);
            ldm_x4(bh[p], b_hi + off);
            ldm_x4(bl[p], b_lo + off);
        }
#pragma unroll
        for (int i = 0; i < 2; i++)
#pragma unroll
            for (int p = 0; p < 4; p++) {
                mma_bf16(C[i][2 * p],     ah[i], &bh[p][0]);
                mma_bf16(C[i][2 * p],     ah[i], &bl[p][0]);
                mma_bf16(C[i][2 * p],     al[i], &bh[p][0]);
                mma_bf16(C[i][2 * p + 1], ah[i], &bh[p][2]);
                mma_bf16(C[i][2 * p + 1], ah[i], &bl[p][2]);
                mma_bf16(C[i][2 * p + 1], al[i], &bh[p][2]);
            }
    }
}

// ---------------------------------------------------------------------------
// prep_p kernel: P1 = h@W1_top + b1, P2 = h@W1_bot   (per 128-node tile)
// ---------------------------------------------------------------------------
__global__ __launch_bounds__(256, 2)
void prep_p_kernel(const float* __restrict__ b1, int layer) {
    extern __shared__ char smem[];
    const uint32_t sbase = smem_u32(smem);
    const int tid = threadIdx.x;
    const int lane = tid & 31;
    const int wid = tid >> 5;
    const int n0 = blockIdx.x * ET;

    const int srow = tid >> 1;
    const int shalf = tid & 1;
    const int snode = n0 + srow;
    const int scn = snode < N_NODES ? snode : (N_NODES - 1);

    const int r0 = (wid >> 1) * 32;
    const int c0w = (wid & 1) * 64;

    const uint32_t pah = sbase + PA_H + srow * (SA1 * 2) + shalf * 64;
    const uint32_t pal = sbase + PA_L + srow * (SA1 * 2) + shalf * 64;
    const uint32_t pbh = sbase + PB_H + srow * (SB * 2) + shalf * 64;
    const uint32_t pbl = sbase + PB_L + srow * (SB * 2) + shalf * 64;

    for (int out = 0; out < 2; out++) {
        float C[2][8][4];
#pragma unroll
        for (int i = 0; i < 2; i++)
#pragma unroll
            for (int j = 0; j < 8; j++)
#pragma unroll
                for (int q = 0; q < 4; q++) C[i][j][q] = 0.0f;

        for (int kc = 0; kc < 2; kc++) {
            {
                size_t goff = (size_t)scn * H + kc * 64 + shalf * 32;
                const __nv_bfloat16* sh = &g_hhi[goff];
                const __nv_bfloat16* sl = &g_hlo[goff];
#pragma unroll
                for (int i = 0; i < 4; i++) {
                    cp16(pah + i * 16, sh + i * 8);
                    cp16(pal + i * 16, sl + i * 8);
                }
            }
            {
                int koff = out * 128 + kc * 64 + shalf * 32;
                const __nv_bfloat16* sh = &g_ew1t[layer][0][srow][koff];
                const __nv_bfloat16* sl = &g_ew1t[layer][1][srow][koff];
#pragma unroll
                for (int i = 0; i < 4; i++) {
                    cp16(pbh + i * 16, sh + i * 8);
                    cp16(pbl + i * 16, sl + i * 8);
                }
            }
            cp_commit_wait();
            __syncthreads();
            mma_chunk(sbase + PA_H, sbase + PA_L, SA1,
                      sbase + PB_H, sbase + PB_L, SB, C, r0, c0w, lane);
            __syncthreads();
        }

        float* dst = out ? g_p2 : g_p1;
#pragma unroll
        for (int i = 0; i < 2; i++) {
            int row = r0 + i * 16 + (lane >> 2);
            int nd0 = n0 + row;
            int nd1 = n0 + row + 8;
#pragma unroll
            for (int j = 0; j < 8; j++) {
                int col = c0w + j * 8 + (lane & 3) * 2;
                float bb0 = out ? 0.0f : b1[col];
                float bb1 = out ? 0.0f : b1[col + 1];
                if (nd0 < N_NODES)
                    *(float2*)&dst[(size_t)nd0 * H + col] =
                        make_float2(C[i][j][0] + bb0, C[i][j][1] + bb1);
                if (nd1 < N_NODES)
                    *(float2*)&dst[(size_t)nd1 * H + col] =
                        make_float2(C[i][j][2] + bb0, C[i][j][3] + bb1);
            }
        }
    }
}

// ---------------------------------------------------------------------------
// Edge kernel (resident-B, occ-2, semi-persistent): tile = 64 edges.
// e = relu(P1[src] + P2[dst]) @ W2 + b2 ; scatter into g_agg.
// ---------------------------------------------------------------------------
__global__ __launch_bounds__(256, 2)
void edge_kernel_res(const float* __restrict__ b2, int layer) {
    extern __shared__ char smem[];
    const uint32_t sbase = smem_u32(smem);
    const int tid = threadIdx.x;
    const int lane = tid & 31;
    const int wid = tid >> 5;
    const int G = gridDim.x;

    // warp tile: rows r0..r0+15, cols c0w..c0w+63
    const int r0 = (wid >> 1) * 16;
    const int c0w = (wid & 1) * 64;

    // ---- stage resident B = W2^T hi/lo into [128][SE2] (once per CTA)
    {
        const int srow = tid >> 1;
        const int shalf = tid & 1;
        const __nv_bfloat16* sh = &g_ew2t[layer][0][srow][shalf * 64];
        const __nv_bfloat16* sl = &g_ew2t[layer][1][srow][shalf * 64];
        uint32_t dh = sbase + E_BH + (uint32_t)(srow * SE2 + shalf * 64) * 2;
        uint32_t dl = sbase + E_BL + (uint32_t)(srow * SE2 + shalf * 64) * 2;
#pragma unroll
        for (int i = 0; i < 8; i++) {
            cp16(dh + i * 16, sh + i * 8);
            cp16(dl + i * 16, sl + i * 8);
        }
    }

    // bias pairs
    float2 bb[8];
#pragma unroll
    for (int j = 0; j < 8; j++)
        bb[j] = *(const float2*)&b2[c0w + j * 8 + (lane & 3) * 2];

    // build role: 4 threads/row, 32 cols each
    const int br = tid >> 2;
    const int bq = tid & 3;

    // mma fragment addressing
    const int arow = lane & 15;
    const int acol = (lane >> 4) * 8;
    const int brow = (lane & 7) + ((lane >> 4) << 3);
    const int bcol = ((lane >> 3) & 1) * 8;

    bool firstIt = true;
    for (int t = blockIdx.x; t < NT2; t += G) {
        // ---- build A2 = split(relu(P1[src] + P2[dst]))
        {
            int e = t * ET2 + br;
            int src = g_src[e];
            int dst = g_dst[e];
            const float4* p1 = (const float4*)&g_p1[(size_t)src * H + bq * 32];
            const float4* p2 = (const float4*)&g_p2[(size_t)dst * H + bq * 32];
            char* ah = smem + E_A2H + (br * SE2 + bq * 32) * 2;
            char* al = smem + E_A2L + (br * SE2 + bq * 32) * 2;
#pragma unroll
            for (int i = 0; i < 8; i++) {
                float4 a = p1[i];
                float4 b = p2[i];
                float v0 = fmaxf(a.x + b.x, 0.0f);
                float v1 = fmaxf(a.y + b.y, 0.0f);
                float v2 = fmaxf(a.z + b.z, 0.0f);
                float v3 = fmaxf(a.w + b.w, 0.0f);
                uint32_t h01, l01, h23, l23;
                split2(v0, v1, h01, l01);
                split2(v2, v3, h23, l23);
                *(uint2*)(ah + i * 8) = make_uint2(h01, h23);
                *(uint2*)(al + i * 8) = make_uint2(l01, l23);
            }
        }
        if (firstIt) { cp_commit_wait(); firstIt = false; }
        __syncthreads();

        // ---- GEMM: full K=128, resident B
        float C[8][4];
#pragma unroll
        for (int j = 0; j < 8; j++)
#pragma unroll
            for (int q = 0; q < 4; q++) C[j][q] = 0.0f;

#pragma unroll
        for (int ks = 0; ks < 8; ks++) {
            uint32_t ah[4], al[4], bh[4][4], bl[4][4];
            uint32_t offa = (uint32_t)(((r0 + arow) * SE2 + ks * 16 + acol) * 2);
            ldm_x4(ah, sbase + E_A2H + offa);
            ldm_x4(al, sbase + E_A2L + offa);
#pragma unroll
            for (int p = 0; p < 4; p++) {
                uint32_t offb = (uint32_t)(((c0w + p * 16 + brow) * SE2 + ks * 16 + bcol) * 2);
                ldm_x4(bh[p], sbase + E_BH + offb);
                ldm_x4(bl[p], sbase + E_BL + offb);
            }
#pragma unroll
            for (int p = 0; p < 4; p++) {
                mma_bf16(C[2 * p],     ah, &bh[p][0]);
                mma_bf16(C[2 * p],     ah, &bl[p][0]);
                mma_bf16(C[2 * p],     al, &bh[p][0]);
                mma_bf16(C[2 * p + 1], ah, &bh[p][2]);
                mma_bf16(C[2 * p + 1], ah, &bl[p][2]);
                mma_bf16(C[2 * p + 1], al, &bh[p][2]);
            }
        }

        // ---- scatter
        {
            int row0 = r0 + (lane >> 2);
            int row1 = row0 + 8;
            int d0 = g_dst[t * ET2 + row0];
            int d1 = g_dst[t * ET2 + row1];
#pragma unroll
            for (int j = 0; j < 8; j++) {
                int col = c0w + j * 8 + (lane & 3) * 2;
                red_add_v2(&g_agg[(size_t)d0 * H + col],
                           C[j][0] + bb[j].x, C[j][1] + bb[j].y);
                red_add_v2(&g_agg[(size_t)d1 * H + col],
                           C[j][2] + bb[j].x, C[j][3] + bb[j].y);
            }
        }
        __syncthreads();   // mma reads done before next build overwrites A2
    }
}

// ---------------------------------------------------------------------------
// Node kernel (tensor-core mma.sync): 128 nodes/block; h += MLP([h,agg]);
// zeroes agg in place; writes fp32 h + bf16 hi/lo split for next layer.
// ---------------------------------------------------------------------------
__global__ __launch_bounds__(256, 2)
void node_kernel_mma(const float* __restrict__ b1,
                     const float* __restrict__ b2, int layer) {
    extern __shared__ char smem[];
    const uint32_t sbase = smem_u32(smem);
    const int tid = threadIdx.x;
    const int lane = tid & 31;
    const int wid = tid >> 5;
    const int n0 = blockIdx.x * ET;

    const int srow = tid >> 1;
    const int shalf = tid & 1;
    const int snode = n0 + srow;
    const int scn = snode < N_NODES ? snode : (N_NODES - 1);

    const int r0 = (wid >> 1) * 32;
    const int c0w = (wid & 1) * 64;

    const uint32_t a1h = sbase + A1H_OFF + srow * (SA1 * 2) + shalf * 64;
    const uint32_t a1l = sbase + A1L_OFF + srow * (SA1 * 2) + shalf * 64;
    const uint32_t bsh = sbase + BH_OFF + srow * (SB * 2) + shalf * 64;
    const uint32_t bsl = sbase + BL_OFF + srow * (SB * 2) + shalf * 64;

    float C[2][8][4];
#pragma unroll
    for (int i = 0; i < 2; i++)
#pragma unroll
        for (int j = 0; j < 8; j++)
#pragma unroll
            for (int q = 0; q < 4; q++) C[i][j][q] = 0.0f;

    // ================= GEMM1: K=256 ([h | agg]) in 4 chunks =================
    for (int kc = 0; kc < 4; kc++) {
        if (kc < 2) {
            size_t goff = (size_t)scn * H + kc * 64 + shalf * 32;
            const __nv_bfloat16* sh = &g_hhi[goff];
            const __nv_bfloat16* sl = &g_hlo[goff];
#pragma unroll
            for (int i = 0; i < 4; i++) {
                cp16(a1h + i * 16, sh + i * 8);
                cp16(a1l + i * 16, sl + i * 8);
            }
        } else {
            // agg chunks: split on the fly + zero in place
            float4* hp = (float4*)&g_agg[(size_t)scn * H + (kc & 1) * 64 + shalf * 32];
            uint32_t ph[16], pl[16];
#pragma unroll
            for (int i = 0; i < 8; i++) {
                float4 v = hp[i];
                split2(v.x, v.y, ph[2 * i],     pl[2 * i]);
                split2(v.z, v.w, ph[2 * i + 1], pl[2 * i + 1]);
            }
            if (snode < N_NODES) {
                float4 z = make_float4(0.f, 0.f, 0.f, 0.f);
#pragma unroll
                for (int i = 0; i < 8; i++) hp[i] = z;
            }
            uint4* dh = (uint4*)(smem + A1H_OFF + srow * (SA1 * 2) + shalf * 64);
            uint4* dl = (uint4*)(smem + A1L_OFF + srow * (SA1 * 2) + shalf * 64);
#pragma unroll
            for (int i = 0; i < 4; i++) {
                dh[i] = make_uint4(ph[4 * i], ph[4 * i + 1], ph[4 * i + 2], ph[4 * i + 3]);
                dl[i] = make_uint4(pl[4 * i], pl[4 * i + 1], pl[4 * i + 2], pl[4 * i + 3]);
            }
        }
        {
            const __nv_bfloat16* sh = &g_nw1t[layer][0][srow][kc * 64 + shalf * 32];
            const __nv_bfloat16* sl = &g_nw1t[layer][1][srow][kc * 64 + shalf * 32];
#pragma unroll
            for (int i = 0; i < 4; i++) {
                cp16(bsh + i * 16, sh + i * 8);
                cp16(bsl + i * 16, sl + i * 8);
            }
        }
        cp_commit_wait();
        __syncthreads();
        mma_chunk(sbase + A1H_OFF, sbase + A1L_OFF, SA1,
                  sbase + BH_OFF, sbase + BL_OFF, SB, C, r0, c0w, lane);
        __syncthreads();
    }

    // ===== Epilogue1 + stage GEMM2 B(kc=0) =====
    {
        const __nv_bfloat16* sh = &g_nw2t[layer][0][srow][shalf * 32];
        const __nv_bfloat16* sl = &g_nw2t[layer][1][srow][shalf * 32];
#pragma unroll
        for (int i = 0; i < 4; i++) {
            cp16(bsh + i * 16, sh + i * 8);
            cp16(bsl + i * 16, sl + i * 8);
        }
    }
#pragma unroll
    for (int i = 0; i < 2; i++)
#pragma unroll
        for (int j = 0; j < 8; j++) {
            int col = c0w + j * 8 + (lane & 3) * 2;
            int row = r0 + i * 16 + (lane >> 2);
            float bb0 = b1[col], bb1 = b1[col + 1];
            uint32_t hi, lo;
            split2(fmaxf(C[i][j][0] + bb0, 0.0f), fmaxf(C[i][j][1] + bb1, 0.0f), hi, lo);
            *(uint32_t*)(smem + A2H_OFF + row * (SA2 * 2) + col * 2) = hi;
            *(uint32_t*)(smem + A2L_OFF + row * (SA2 * 2) + col * 2) = lo;
            split2(fmaxf(C[i][j][2] + bb0, 0.0f), fmaxf(C[i][j][3] + bb1, 0.0f), hi, lo);
            *(uint32_t*)(smem + A2H_OFF + (row + 8) * (SA2 * 2) + col * 2) = hi;
            *(uint32_t*)(smem + A2L_OFF + (row + 8) * (SA2 * 2) + col * 2) = lo;
        }
    cp_commit_wait();
    __syncthreads();

    // ================= GEMM2: K=128 in 2 chunks =================
#pragma unroll
    for (int i = 0; i < 2; i++)
#pragma unroll
        for (int j = 0; j < 8; j++)
#pragma unroll
            for (int q = 0; q < 4; q++) C[i][j][q] = 0.0f;

    for (int kc = 0; kc < 2; kc++) {
        if (kc > 0) {
            const __nv_bfloat16* sh = &g_nw2t[layer][0][srow][kc * 64 + shalf * 32];
            const __nv_bfloat16* sl = &g_nw2t[layer][1][srow][kc * 64 + shalf * 32];
#pragma unroll
            for (int i = 0; i < 4; i++) {
                cp16(bsh + i * 16, sh + i * 8);
                cp16(bsl + i * 16, sl + i * 8);
            }
            cp_commit_wait();
            __syncthreads();
        }
        mma_chunk(sbase + A2H_OFF + kc * 128, sbase + A2L_OFF + kc * 128, SA2,
                  sbase + BH_OFF, sbase + BL_OFF, SB, C, r0, c0w, lane);
        __syncthreads();
    }

    // ======== Epilogue2: residual h += C + b2; write fp32 + bf16 split ========
#pragma unroll
    for (int i = 0; i < 2; i++) {
        int row = r0 + i * 16 + (lane >> 2);
        int nd0 = n0 + row;
        int nd1 = n0 + row + 8;
#pragma unroll
        for (int j = 0; j < 8; j++) {
            int col = c0w + j * 8 + (lane & 3) * 2;
            float bb0 = b2[col], bb1 = b2[col + 1];
            if (nd0 < N_NODES) {
                size_t off = (size_t)nd0 * H + col;
                float2* p = (float2*)&g_h[off];
                float2 v = *p;
                v.x += C[i][j][0] + bb0;
                v.y += C[i][j][1] + bb1;
                *p = v;
                uint32_t hi, lo;
                split2(v.x, v.y, hi, lo);
                *(uint32_t*)&g_hhi[off] = hi;
                *(uint32_t*)&g_hlo[off] = lo;
            }
            if (nd1 < N_NODES) {
                size_t off = (size_t)nd1 * H + col;
                float2* p = (float2*)&g_h[off];
                float2 v = *p;
                v.x += C[i][j][2] + bb0;
                v.y += C[i][j][3] + bb1;
                *p = v;
                uint32_t hi, lo;
                split2(v.x, v.y, hi, lo);
                *(uint32_t*)&g_hhi[off] = hi;
                *(uint32_t*)&g_hlo[off] = lo;
            }
        }
    }
}

// ---------------------------------------------------------------------------
// Decoder
// ---------------------------------------------------------------------------
__global__ void dec_kernel(const float* __restrict__ w,
                           const float* __restrict__ b,
                           float* __restrict__ out) {
    int idx = blockIdx.x * blockDim.x + threadIdx.x;
    if (idx >= N_NODES * NODE_OUT) return;
    int node = idx / NODE_OUT;
    int j = idx - node * NODE_OUT;
    float acc = b[j];
    const float* hp = &g_h[(size_t)node * H];
#pragma unroll 8
    for (int k = 0; k < H; k++)
        acc = fmaf(hp[k], w[k * NODE_OUT + j], acc);
    out[idx] = acc;
}

// ---------------------------------------------------------------------------
extern "C" void kernel_launch(void* const* d_in, const int* in_sizes, int n_in,
                              void* d_out, int out_size) {
    const float* x      = (const float*)d_in[0];
    const void*  ei     = d_in[1];
    const float* enc_w  = (const float*)d_in[2];
    const float* enc_b  = (const float*)d_in[3];
    const float* dec_w  = (const float*)d_in[4];
    const float* dec_b  = (const float*)d_in[5];
    const float* e_w1   = (const float*)d_in[6];
    const float* e_b1   = (const float*)d_in[7];
    const float* e_w2   = (const float*)d_in[8];
    const float* e_b2   = (const float*)d_in[9];
    const float* n_w1   = (const float*)d_in[10];
    const float* n_b1   = (const float*)d_in[11];
    const float* n_w2   = (const float*)d_in[12];
    const float* n_b2   = (const float*)d_in[13];
    float*       out    = (float*)d_out;

    static int nsm = 0;
    if (!nsm) {
        cudaFuncSetAttribute(edge_kernel_res, cudaFuncAttributeMaxDynamicSharedMemorySize,
                             E_SMEM);
        cudaFuncSetAttribute(node_kernel_mma, cudaFuncAttributeMaxDynamicSharedMemorySize,
                             NODE_SMEM);
        cudaFuncSetAttribute(prep_p_kernel, cudaFuncAttributeMaxDynamicSharedMemorySize,
                             PREP_SMEM);
        cudaDeviceGetAttribute(&nsm, cudaDevAttrMultiProcessorCount, 0);
        if (nsm <= 0) nsm = 148;
    }

    detect_kernel<<<1, 32>>>(ei);
    convert_kernel<<<(2 * N_EDGES + 255) / 256, 256>>>(ei);
    prep_w_kernel<<<(2 * N_LAYERS * (2 * H * H + H * H) + 255) / 256, 256>>>(
        e_w1, e_w2, n_w1, n_w2);
    enc_kernel<<<(N_NODES * H + 255) / 256, 256>>>(x, enc_w, enc_b);

    const int node_blocks = (N_NODES + ET - 1) / ET;
    for (int l = 0; l < N_LAYERS; l++) {
        prep_p_kernel<<<node_blocks, 256, PREP_SMEM>>>(e_b1 + (size_t)l * H, l);
        edge_kernel_res<<<2 * nsm, 256, E_SMEM>>>(e_b2 + (size_t)l * H, l);
        node_kernel_mma<<<node_blocks, 256, NODE_SMEM>>>(
            n_b1 + (size_t)l * H, n_b2 + (size_t)l * H, l);
    }

    dec_kernel<<<(N_NODES * NODE_OUT + 255) / 256, 256>>>(dec_w, dec_b, out);
}